// round 11
// baseline (speedup 1.0000x reference)
#include <cuda_runtime.h>
#include <cuda_fp16.h>

#define ND        128
#define MAXN      50016
#define MAXE      1600000
#define SCANB     1024
#define MAXBLK    64

// -------- device scratch (no allocation allowed) --------
// g_deg/g_cnt obey a zero-restore protocol: zero at module load, k_deg
// accumulates, k_scanA consumes AND re-zeroes them, so every graph replay
// sees the same initial state. (Self-loop +1 folded into k_scanA.)
__device__ float g_deg[MAXN];
__device__ float g_dinv[MAXN];
__device__ int   g_cnt[MAXN];
__device__ int   g_rowptr[MAXN + 1];
__device__ int   g_bsum[MAXBLK];
__device__ int   g_rank[MAXE];          // per-edge rank within its dst segment
__device__ uint2 g_csr[MAXE];           // packed {src, val_bits}, val = ew*dinv[src]
__device__ __align__(256) float  g_bufA [50000 * ND];  // fp32: final agg out
__device__ __align__(256) __half g_bufH [50000 * ND];  // fp16: messages ping
__device__ __align__(256) __half g_bufH2[50000 * ND];  // fp16: messages pong

__device__ __forceinline__ unsigned saddr(const void* p) {
    return (unsigned)__cvta_generic_to_shared(p);
}

__device__ __forceinline__ float4 h4_to_f4(uint2 u) {
    __half2 a = *reinterpret_cast<__half2*>(&u.x);
    __half2 b = *reinterpret_cast<__half2*>(&u.y);
    float2 fa = __half22float2(a);
    float2 fb = __half22float2(b);
    return make_float4(fa.x, fa.y, fb.x, fb.y);
}

// -------- degree + per-dst edge count + rank (buffers pre-zeroed) ------
__global__ void k_deg(const int* __restrict__ dst, const float* __restrict__ ew, int E) {
    int e = blockIdx.x * blockDim.x + threadIdx.x;
    if (e < E) {
        int d = dst[e];
        atomicAdd(&g_deg[d], ew[e]);
        g_rank[e] = atomicAdd(&g_cnt[d], 1);   // rank doubles as the CSR slot
    }
}

// -------- scan phase A: block-local inclusive scan + dinv + zero-restore ----
__global__ void k_scanA(int n) {
    __shared__ int warp_sums[32];
    int tid = threadIdx.x;
    int lane = tid & 31, wid = tid >> 5;
    int i = blockIdx.x * SCANB + tid;
    int x = 0;
    if (i < n) {
        float d = g_deg[i] + 1.0f;       // implicit self-loop (weight 1); d >= 1
        g_dinv[i] = rsqrtf(d);
        g_deg[i] = 0.0f;                 // restore protocol invariant
        x = g_cnt[i];
        g_cnt[i] = 0;                    // restore protocol invariant
    }
    #pragma unroll
    for (int o = 1; o < 32; o <<= 1) {
        int y = __shfl_up_sync(0xFFFFFFFFu, x, o);
        if (lane >= o) x += y;
    }
    if (lane == 31) warp_sums[wid] = x;
    __syncthreads();
    if (wid == 0) {
        int w = warp_sums[lane];
        #pragma unroll
        for (int o = 1; o < 32; o <<= 1) {
            int y = __shfl_up_sync(0xFFFFFFFFu, w, o);
            if (lane >= o) w += y;
        }
        warp_sums[lane] = w;
    }
    __syncthreads();
    int incl = x + (wid > 0 ? warp_sums[wid - 1] : 0);
    if (i < n) g_rowptr[i + 1] = incl;
    if (tid == SCANB - 1) g_bsum[blockIdx.x] = incl;
}

// -------- phase C: per-block offset via local reduce of block sums ---------
__global__ void k_scanC(int n) {
    __shared__ int s_off;
    if (threadIdx.x < 32) {
        int acc = 0;
        for (int base = 0; base < (int)blockIdx.x; base += 32) {
            int idx = base + (int)threadIdx.x;
            int v = (idx < (int)blockIdx.x) ? g_bsum[idx] : 0;
            #pragma unroll
            for (int o = 16; o > 0; o >>= 1)
                v += __shfl_xor_sync(0xFFFFFFFFu, v, o);
            acc += v;
        }
        if (threadIdx.x == 0) s_off = acc;
    }
    __syncthreads();
    int off = s_off;
    int i = blockIdx.x * SCANB + threadIdx.x;
    if (i < n) g_rowptr[i + 1] += off;
    if (i == 0) g_rowptr[0] = 0;
}

// -------- scatter edges into CSR (by dst): NO atomics, packed 8B store -----
__global__ void k_csr(const int* __restrict__ src, const int* __restrict__ dst,
                      const float* __restrict__ ew, int E) {
    int e = blockIdx.x * blockDim.x + threadIdx.x;
    if (e < E) {
        int s = src[e], d = dst[e];
        int p = g_rowptr[d] + g_rank[e];
        uint2 u;
        u.x = (unsigned)s;
        float v = g_dinv[s] * ew[e];
        u.y = __float_as_uint(v);
        g_csr[p] = u;
    }
}

// -------- shared agg body: accumulate over a node's CSR row ---------------
__device__ __forceinline__ float4 agg_row(const uint2* __restrict__ XWv,
                                          int node, int lane) {
    float di = g_dinv[node];
    float4 a = h4_to_f4(XWv[node * 32 + lane]);
    float4 acc = make_float4(a.x * di, a.y * di, a.z * di, a.w * di);
    int e0 = g_rowptr[node], e1 = g_rowptr[node + 1];
    int e = e0;
    for (; e + 8 <= e1; e += 8) {
        uint2 cv[8]; uint2 u[8];
        #pragma unroll
        for (int j = 0; j < 8; j++) cv[j] = g_csr[e + j];
        #pragma unroll
        for (int j = 0; j < 8; j++) u[j] = XWv[cv[j].x * 32 + lane];
        #pragma unroll
        for (int j = 0; j < 8; j++) {
            float v = __uint_as_float(cv[j].y);
            float4 m = h4_to_f4(u[j]);
            acc.x = fmaf(v, m.x, acc.x); acc.y = fmaf(v, m.y, acc.y);
            acc.z = fmaf(v, m.z, acc.z); acc.w = fmaf(v, m.w, acc.w);
        }
    }
    if (e + 4 <= e1) {
        uint2 cv[4]; uint2 u[4];
        #pragma unroll
        for (int j = 0; j < 4; j++) cv[j] = g_csr[e + j];
        #pragma unroll
        for (int j = 0; j < 4; j++) u[j] = XWv[cv[j].x * 32 + lane];
        #pragma unroll
        for (int j = 0; j < 4; j++) {
            float v = __uint_as_float(cv[j].y);
            float4 m = h4_to_f4(u[j]);
            acc.x = fmaf(v, m.x, acc.x); acc.y = fmaf(v, m.y, acc.y);
            acc.z = fmaf(v, m.z, acc.z); acc.w = fmaf(v, m.w, acc.w);
        }
        e += 4;
    }
    for (; e < e1; e++) {
        uint2 cv = g_csr[e];
        float v = __uint_as_float(cv.y);
        float4 m = h4_to_f4(XWv[cv.x * 32 + lane]);
        acc.x = fmaf(v, m.x, acc.x); acc.y = fmaf(v, m.y, acc.y);
        acc.z = fmaf(v, m.z, acc.z); acc.w = fmaf(v, m.w, acc.w);
    }
    acc.x *= di; acc.y *= di; acc.z *= di; acc.w *= di;
    return acc;
}

// -------- FUSED interior layer: agg(+bias+relu) -> smem -> GEMM -> fp16 ----
// Block handles 128 nodes. Phase 1: 8 warps aggregate 16 nodes each into Xs.
// Phase 2: ldmatrix/HMMA GEMM straight from smem. Removes the gmem roundtrip.
__global__ void __launch_bounds__(256) k_fused(const __half* __restrict__ XW,
                                               const float* __restrict__ bias,
                                               const float* __restrict__ W,
                                               __half* __restrict__ Y, int n) {
    __shared__ __align__(16) __half Xs[128][136];   // full K, pitch 17x16B
    __shared__ __align__(16) __half Ws[32][136];
    const int tid  = threadIdx.x;
    const int warp = tid >> 5, lane = tid & 31;
    const int gid  = lane >> 2, tig = lane & 3;
    const int row0 = blockIdx.x * 128;
    const int wr   = warp * 16;

    // ---- phase 1: aggregation (bias + relu fused; interior layers only) ----
    const uint2* XWv = reinterpret_cast<const uint2*>(XW);
    float4 b = reinterpret_cast<const float4*>(bias)[lane];
    for (int i = 0; i < 16; i++) {
        int m = wr + i;
        int node = row0 + m;
        float4 acc = make_float4(0.f, 0.f, 0.f, 0.f);
        if (node < n) {
            acc = agg_row(XWv, node, lane);
            acc.x = fmaxf(acc.x + b.x, 0.f);
            acc.y = fmaxf(acc.y + b.y, 0.f);
            acc.z = fmaxf(acc.z + b.z, 0.f);
            acc.w = fmaxf(acc.w + b.w, 0.f);
        }
        *reinterpret_cast<__half2*>(&Xs[m][lane * 4])     = __floats2half2_rn(acc.x, acc.y);
        *reinterpret_cast<__half2*>(&Xs[m][lane * 4 + 2]) = __floats2half2_rn(acc.z, acc.w);
    }
    __syncthreads();

    // ---- phase 2: GEMM from smem ----
    float acc[16][4];
    #pragma unroll
    for (int t = 0; t < 16; t++)
        #pragma unroll
        for (int j = 0; j < 4; j++) acc[t][j] = 0.0f;

    for (int kc = 0; kc < ND; kc += 32) {
        #pragma unroll
        for (int i = 0; i < 4; i++) {
            int idx = tid + i * 256;            // 0..1023 float4s
            int k   = idx >> 5;                 // 0..31
            int c4  = (idx & 31) * 4;
            float4 v = *reinterpret_cast<const float4*>(W + (kc + k) * ND + c4);
            *reinterpret_cast<__half2*>(&Ws[k][c4])     = __floats2half2_rn(v.x, v.y);
            *reinterpret_cast<__half2*>(&Ws[k][c4 + 2]) = __floats2half2_rn(v.z, v.w);
        }
        __syncthreads();
        #pragma unroll
        for (int ks = 0; ks < 2; ks++) {
            int k0  = kc + ks * 16;
            int k0l = ks * 16;
            unsigned a0, a1, a2, a3;
            unsigned aadr = saddr(&Xs[wr + (lane & 15)][k0 + (lane >> 4) * 8]);
            asm volatile("ldmatrix.sync.aligned.m8n8.x4.shared.b16 {%0,%1,%2,%3}, [%4];"
                         : "=r"(a0), "=r"(a1), "=r"(a2), "=r"(a3) : "r"(aadr));
            #pragma unroll
            for (int np = 0; np < 8; np++) {
                unsigned b0, b1, b2, b3;
                unsigned badr = saddr(&Ws[k0l + (lane & 15)][np * 16 + (lane >> 4) * 8]);
                asm volatile("ldmatrix.sync.aligned.m8n8.x4.trans.shared.b16 {%0,%1,%2,%3}, [%4];"
                             : "=r"(b0), "=r"(b1), "=r"(b2), "=r"(b3) : "r"(badr));
                asm volatile(
                    "mma.sync.aligned.m16n8k16.row.col.f32.f16.f16.f32 "
                    "{%0,%1,%2,%3},{%4,%5,%6,%7},{%8,%9},{%0,%1,%2,%3};"
                    : "+f"(acc[np * 2][0]), "+f"(acc[np * 2][1]),
                      "+f"(acc[np * 2][2]), "+f"(acc[np * 2][3])
                    : "r"(a0), "r"(a1), "r"(a2), "r"(a3), "r"(b0), "r"(b1));
                asm volatile(
                    "mma.sync.aligned.m16n8k16.row.col.f32.f16.f16.f32 "
                    "{%0,%1,%2,%3},{%4,%5,%6,%7},{%8,%9},{%0,%1,%2,%3};"
                    : "+f"(acc[np * 2 + 1][0]), "+f"(acc[np * 2 + 1][1]),
                      "+f"(acc[np * 2 + 1][2]), "+f"(acc[np * 2 + 1][3])
                    : "r"(a0), "r"(a1), "r"(a2), "r"(a3), "r"(b2), "r"(b3));
            }
        }
        __syncthreads();
    }
    int r0 = row0 + wr + gid;
    int r1 = r0 + 8;
    #pragma unroll
    for (int nt = 0; nt < 16; nt++) {
        int col = nt * 8 + tig * 2;
        if (r0 < n)
            *reinterpret_cast<__half2*>(Y + r0 * ND + col) =
                __floats2half2_rn(acc[nt][0], acc[nt][1]);
        if (r1 < n)
            *reinterpret_cast<__half2*>(Y + r1 * ND + col) =
                __floats2half2_rn(acc[nt][2], acc[nt][3]);
    }
}

// -------- layer-0 GEMM (fp32 input) via ldmatrix + mma.m16n8k16 ------------
__global__ void __launch_bounds__(256) k_gemm(const float* __restrict__ X,
                                              const float* __restrict__ W,
                                              __half* __restrict__ Y, int n) {
    __shared__ __align__(16) __half Xs[128][72];
    __shared__ __align__(16) __half Ws[64][136];
    const int tid  = threadIdx.x;
    const int warp = tid >> 5, lane = tid & 31;
    const int gid  = lane >> 2, tig = lane & 3;
    const int row0 = blockIdx.x * 128;
    const int wr   = warp * 16;

    float acc[16][4];
    #pragma unroll
    for (int t = 0; t < 16; t++)
        #pragma unroll
        for (int j = 0; j < 4; j++) acc[t][j] = 0.0f;

    for (int kc = 0; kc < ND; kc += 64) {
        #pragma unroll
        for (int i = 0; i < 8; i++) {
            int idx = tid + i * 256;
            int k   = idx >> 5;
            int c4  = (idx & 31) * 4;
            float4 v = *reinterpret_cast<const float4*>(W + (kc + k) * ND + c4);
            *reinterpret_cast<__half2*>(&Ws[k][c4])     = __floats2half2_rn(v.x, v.y);
            *reinterpret_cast<__half2*>(&Ws[k][c4 + 2]) = __floats2half2_rn(v.z, v.w);
        }
        #pragma unroll
        for (int i = 0; i < 8; i++) {
            int idx = tid + i * 256;
            int m   = idx >> 4;
            int j4  = (idx & 15) * 4;
            float4 v = make_float4(0.f, 0.f, 0.f, 0.f);
            if (row0 + m < n)
                v = *reinterpret_cast<const float4*>(X + (row0 + m) * ND + kc + j4);
            *reinterpret_cast<__half2*>(&Xs[m][j4])     = __floats2half2_rn(v.x, v.y);
            *reinterpret_cast<__half2*>(&Xs[m][j4 + 2]) = __floats2half2_rn(v.z, v.w);
        }
        __syncthreads();
        #pragma unroll
        for (int ks = 0; ks < 4; ks++) {
            int k0 = ks * 16;
            unsigned a0, a1, a2, a3;
            unsigned aadr = saddr(&Xs[wr + (lane & 15)][k0 + (lane >> 4) * 8]);
            asm volatile("ldmatrix.sync.aligned.m8n8.x4.shared.b16 {%0,%1,%2,%3}, [%4];"
                         : "=r"(a0), "=r"(a1), "=r"(a2), "=r"(a3) : "r"(aadr));
            #pragma unroll
            for (int np = 0; np < 8; np++) {
                unsigned b0, b1, b2, b3;
                unsigned badr = saddr(&Ws[k0 + (lane & 15)][np * 16 + (lane >> 4) * 8]);
                asm volatile("ldmatrix.sync.aligned.m8n8.x4.trans.shared.b16 {%0,%1,%2,%3}, [%4];"
                             : "=r"(b0), "=r"(b1), "=r"(b2), "=r"(b3) : "r"(badr));
                asm volatile(
                    "mma.sync.aligned.m16n8k16.row.col.f32.f16.f16.f32 "
                    "{%0,%1,%2,%3},{%4,%5,%6,%7},{%8,%9},{%0,%1,%2,%3};"
                    : "+f"(acc[np * 2][0]), "+f"(acc[np * 2][1]),
                      "+f"(acc[np * 2][2]), "+f"(acc[np * 2][3])
                    : "r"(a0), "r"(a1), "r"(a2), "r"(a3), "r"(b0), "r"(b1));
                asm volatile(
                    "mma.sync.aligned.m16n8k16.row.col.f32.f16.f16.f32 "
                    "{%0,%1,%2,%3},{%4,%5,%6,%7},{%8,%9},{%0,%1,%2,%3};"
                    : "+f"(acc[np * 2 + 1][0]), "+f"(acc[np * 2 + 1][1]),
                      "+f"(acc[np * 2 + 1][2]), "+f"(acc[np * 2 + 1][3])
                    : "r"(a0), "r"(a1), "r"(a2), "r"(a3), "r"(b2), "r"(b3));
            }
        }
        __syncthreads();
    }
    int r0 = row0 + wr + gid;
    int r1 = r0 + 8;
    #pragma unroll
    for (int nt = 0; nt < 16; nt++) {
        int col = nt * 8 + tig * 2;
        if (r0 < n)
            *reinterpret_cast<__half2*>(Y + r0 * ND + col) =
                __floats2half2_rn(acc[nt][0], acc[nt][1]);
        if (r1 < n)
            *reinterpret_cast<__half2*>(Y + r1 * ND + col) =
                __floats2half2_rn(acc[nt][2], acc[nt][3]);
    }
}

// -------- final-layer aggregation: fp32 out, no relu -----------------------
__global__ void __launch_bounds__(256) k_agg(const __half* __restrict__ XW,
                                             const float* __restrict__ bias,
                                             float4* __restrict__ OUT, int n) {
    int node = (blockIdx.x * blockDim.x + threadIdx.x) >> 5;
    int lane = threadIdx.x & 31;
    if (node >= n) return;
    const uint2* XWv = reinterpret_cast<const uint2*>(XW);
    float4 acc = agg_row(XWv, node, lane);
    float4 b = reinterpret_cast<const float4*>(bias)[lane];
    acc.x += b.x; acc.y += b.y; acc.z += b.z; acc.w += b.w;
    OUT[node * 32 + lane] = acc;
}

// -------- global mean pool: one block (1024 thr) per graph, fused bounds ----
__global__ void __launch_bounds__(1024) k_pool(const float4* __restrict__ h,
                                               const int* __restrict__ batch,
                                               int n, float4* __restrict__ out) {
    __shared__ float4 part[32][32];
    __shared__ int sse[2];
    int g = blockIdx.x;
    if (threadIdx.x < 2) {
        int target = g + threadIdx.x;
        int lo = 0, hi = n;
        while (lo < hi) {
            int mid = (lo + hi) >> 1;
            if (batch[mid] < target) lo = mid + 1; else hi = mid;
        }
        sse[threadIdx.x] = lo;
    }
    __syncthreads();
    int s = sse[0], e = sse[1];
    int rg = threadIdx.x >> 5;
    int ch = threadIdx.x & 31;
    float4 acc = make_float4(0.f, 0.f, 0.f, 0.f);
    for (int i = s + rg; i < e; i += 32) {
        float4 v = h[i * 32 + ch];
        acc.x += v.x; acc.y += v.y; acc.z += v.z; acc.w += v.w;
    }
    part[rg][ch] = acc;
    __syncthreads();
    #pragma unroll
    for (int off = 16; off > 0; off >>= 1) {
        if (rg < off) {
            float4 o = part[rg + off][ch];
            float4 m = part[rg][ch];
            m.x += o.x; m.y += o.y; m.z += o.z; m.w += o.w;
            part[rg][ch] = m;
        }
        __syncthreads();
    }
    if (rg == 0) {
        float inv = 1.0f / (float)((e - s) > 0 ? (e - s) : 1);
        float4 m = part[0][ch];
        m.x *= inv; m.y *= inv; m.z *= inv; m.w *= inv;
        out[g * 32 + ch] = m;
    }
}

extern "C" void kernel_launch(void* const* d_in, const int* in_sizes, int n_in,
                              void* d_out, int out_size) {
    const float* x     = (const float*)d_in[0];
    const int*   ei    = (const int*)d_in[1];
    const float* ew    = (const float*)d_in[2];
    const int*   batch = (const int*)d_in[3];
    const float* W0    = (const float*)d_in[4];
    const float* b0    = (const float*)d_in[5];
    const float* W1    = (const float*)d_in[6];
    const float* b1    = (const float*)d_in[7];
    const float* W2    = (const float*)d_in[8];
    const float* b2    = (const float*)d_in[9];

    int n = in_sizes[0] / ND;
    int E = in_sizes[1] / 2;
    int ngraphs = out_size / ND;
    const int* src = ei;
    const int* dst = ei + E;

    float  *bufA;
    __half *bufH, *bufH2;
    cudaGetSymbolAddress((void**)&bufA,  g_bufA);
    cudaGetSymbolAddress((void**)&bufH,  g_bufH);
    cudaGetSymbolAddress((void**)&bufH2, g_bufH2);

    int eb  = (E + 255) / 256;
    int gb  = (n + 127) / 128;
    int ab  = (int)(((long long)n * 32 + 255) / 256);
    int sbk = (n + SCANB - 1) / SCANB;

    // normalization + CSR build (g_deg/g_cnt zeroed by protocol)
    k_deg<<<eb, 256>>>(dst, ew, E);
    k_scanA<<<sbk, SCANB>>>(n);
    k_scanC<<<sbk, SCANB>>>(n);
    k_csr<<<eb, 256>>>(src, dst, ew, E);

    // layer 0 GEMM: x @ W0 -> messages (fp16)
    k_gemm<<<gb, 256>>>(x, W0, bufH, n);
    // fused interior joints: agg(+b,relu) -> GEMM
    k_fused<<<gb, 256>>>(bufH,  b0, W1, bufH2, n);
    k_fused<<<gb, 256>>>(bufH2, b1, W2, bufH,  n);
    // final aggregation (fp32, no relu)
    k_agg<<<ab, 256>>>(bufH, b2, (float4*)bufA, n);

    // pooling (bounds fused)
    k_pool<<<ngraphs, 1024>>>((const float4*)bufA, batch, n, (float4*)d_out);
}

// round 12
// speedup vs baseline: 1.5444x; 1.5444x over previous
#include <cuda_runtime.h>
#include <cuda_fp16.h>

#define ND        128
#define MAXN      50016
#define MAXE      1600000
#define SCANB     1024
#define MAXBLK    64

// -------- device scratch (no allocation allowed) --------
// g_deg/g_cnt obey a zero-restore protocol: zero at module load, k_deg
// accumulates, k_scanA consumes AND re-zeroes them, so every graph replay
// sees the same initial state. (Self-loop +1 folded into k_scanA.)
__device__ float g_deg[MAXN];
__device__ float g_dinv[MAXN];
__device__ int   g_cnt[MAXN];
__device__ int   g_rowptr[MAXN + 1];
__device__ int   g_bsum[MAXBLK];
__device__ int   g_rank[MAXE];          // per-edge rank within its dst segment
__device__ uint2 g_csr[MAXE];           // packed {src, val_bits}, val = ew*dinv[src]
__device__ __align__(256) __half g_bufH [50000 * ND];  // fp16: messages ping
__device__ __align__(256) __half g_bufH2[50000 * ND];  // fp16: messages pong

__device__ __forceinline__ unsigned saddr(const void* p) {
    return (unsigned)__cvta_generic_to_shared(p);
}

__device__ __forceinline__ float4 h4_to_f4(uint2 u) {
    __half2 a = *reinterpret_cast<__half2*>(&u.x);
    __half2 b = *reinterpret_cast<__half2*>(&u.y);
    float2 fa = __half22float2(a);
    float2 fb = __half22float2(b);
    return make_float4(fa.x, fa.y, fb.x, fb.y);
}

// -------- degree + per-dst edge count + rank (buffers pre-zeroed) ------
__global__ void k_deg(const int* __restrict__ dst, const float* __restrict__ ew, int E) {
    int e = blockIdx.x * blockDim.x + threadIdx.x;
    if (e < E) {
        int d = dst[e];
        atomicAdd(&g_deg[d], ew[e]);
        g_rank[e] = atomicAdd(&g_cnt[d], 1);   // rank doubles as the CSR slot
    }
}

// -------- scan phase A: block-local inclusive scan + dinv + zero-restore ----
__global__ void k_scanA(int n) {
    __shared__ int warp_sums[32];
    int tid = threadIdx.x;
    int lane = tid & 31, wid = tid >> 5;
    int i = blockIdx.x * SCANB + tid;
    int x = 0;
    if (i < n) {
        float d = g_deg[i] + 1.0f;       // implicit self-loop (weight 1); d >= 1
        g_dinv[i] = rsqrtf(d);
        g_deg[i] = 0.0f;                 // restore protocol invariant
        x = g_cnt[i];
        g_cnt[i] = 0;                    // restore protocol invariant
    }
    #pragma unroll
    for (int o = 1; o < 32; o <<= 1) {
        int y = __shfl_up_sync(0xFFFFFFFFu, x, o);
        if (lane >= o) x += y;
    }
    if (lane == 31) warp_sums[wid] = x;
    __syncthreads();
    if (wid == 0) {
        int w = warp_sums[lane];
        #pragma unroll
        for (int o = 1; o < 32; o <<= 1) {
            int y = __shfl_up_sync(0xFFFFFFFFu, w, o);
            if (lane >= o) w += y;
        }
        warp_sums[lane] = w;
    }
    __syncthreads();
    int incl = x + (wid > 0 ? warp_sums[wid - 1] : 0);
    if (i < n) g_rowptr[i + 1] = incl;
    if (tid == SCANB - 1) g_bsum[blockIdx.x] = incl;
}

// -------- phase C: per-block offset via local reduce of block sums ---------
__global__ void k_scanC(int n) {
    __shared__ int s_off;
    if (threadIdx.x < 32) {
        int acc = 0;
        for (int base = 0; base < (int)blockIdx.x; base += 32) {
            int idx = base + (int)threadIdx.x;
            int v = (idx < (int)blockIdx.x) ? g_bsum[idx] : 0;
            #pragma unroll
            for (int o = 16; o > 0; o >>= 1)
                v += __shfl_xor_sync(0xFFFFFFFFu, v, o);
            acc += v;
        }
        if (threadIdx.x == 0) s_off = acc;
    }
    __syncthreads();
    int off = s_off;
    int i = blockIdx.x * SCANB + threadIdx.x;
    if (i < n) g_rowptr[i + 1] += off;
    if (i == 0) g_rowptr[0] = 0;
}

// -------- scatter edges into CSR (by dst): NO atomics, packed 8B store -----
__global__ void k_csr(const int* __restrict__ src, const int* __restrict__ dst,
                      const float* __restrict__ ew, int E) {
    int e = blockIdx.x * blockDim.x + threadIdx.x;
    if (e < E) {
        int s = src[e], d = dst[e];
        int p = g_rowptr[d] + g_rank[e];
        uint2 u;
        u.x = (unsigned)s;
        float v = g_dinv[s] * ew[e];
        u.y = __float_as_uint(v);
        g_csr[p] = u;
    }
}

// -------- fp16 tensor-core GEMM via ldmatrix + mma.m16n8k16 --------
// Block: 128 rows x 128 cols, 8 warps. K chunked by 64.
template<bool HALF_IN>
__global__ void __launch_bounds__(256) k_gemm(const void* __restrict__ Xv,
                                              const float* __restrict__ W,
                                              __half* __restrict__ Y, int n) {
    __shared__ __align__(16) __half Xs[128][72];    // pitch 144B
    __shared__ __align__(16) __half Ws[64][136];    // pitch 272B
    const int tid  = threadIdx.x;
    const int warp = tid >> 5, lane = tid & 31;
    const int gid  = lane >> 2, tig = lane & 3;
    const int row0 = blockIdx.x * 128;
    const int wr   = warp * 16;

    float acc[16][4];
    #pragma unroll
    for (int t = 0; t < 16; t++)
        #pragma unroll
        for (int j = 0; j < 4; j++) acc[t][j] = 0.0f;

    for (int kc = 0; kc < ND; kc += 64) {
        #pragma unroll
        for (int i = 0; i < 8; i++) {
            int idx = tid + i * 256;
            int k   = idx >> 5;
            int c4  = (idx & 31) * 4;
            float4 v = *reinterpret_cast<const float4*>(W + (kc + k) * ND + c4);
            *reinterpret_cast<__half2*>(&Ws[k][c4])     = __floats2half2_rn(v.x, v.y);
            *reinterpret_cast<__half2*>(&Ws[k][c4 + 2]) = __floats2half2_rn(v.z, v.w);
        }
        if (HALF_IN) {
            const __half* X = (const __half*)Xv;
            #pragma unroll
            for (int i = 0; i < 4; i++) {
                int idx = tid + i * 256;
                int m   = idx >> 3;
                int j8  = (idx & 7) * 8;
                uint4 v = make_uint4(0, 0, 0, 0);
                if (row0 + m < n)
                    v = *reinterpret_cast<const uint4*>(X + (row0 + m) * ND + kc + j8);
                *reinterpret_cast<uint4*>(&Xs[m][j8]) = v;
            }
        } else {
            const float* X = (const float*)Xv;
            #pragma unroll
            for (int i = 0; i < 8; i++) {
                int idx = tid + i * 256;
                int m   = idx >> 4;
                int j4  = (idx & 15) * 4;
                float4 v = make_float4(0.f, 0.f, 0.f, 0.f);
                if (row0 + m < n)
                    v = *reinterpret_cast<const float4*>(X + (row0 + m) * ND + kc + j4);
                *reinterpret_cast<__half2*>(&Xs[m][j4])     = __floats2half2_rn(v.x, v.y);
                *reinterpret_cast<__half2*>(&Xs[m][j4 + 2]) = __floats2half2_rn(v.z, v.w);
            }
        }
        __syncthreads();
        #pragma unroll
        for (int ks = 0; ks < 4; ks++) {
            int k0 = ks * 16;
            unsigned a0, a1, a2, a3;
            unsigned aadr = saddr(&Xs[wr + (lane & 15)][k0 + (lane >> 4) * 8]);
            asm volatile("ldmatrix.sync.aligned.m8n8.x4.shared.b16 {%0,%1,%2,%3}, [%4];"
                         : "=r"(a0), "=r"(a1), "=r"(a2), "=r"(a3) : "r"(aadr));
            #pragma unroll
            for (int np = 0; np < 8; np++) {
                unsigned b0, b1, b2, b3;
                unsigned badr = saddr(&Ws[k0 + (lane & 15)][np * 16 + (lane >> 4) * 8]);
                asm volatile("ldmatrix.sync.aligned.m8n8.x4.trans.shared.b16 {%0,%1,%2,%3}, [%4];"
                             : "=r"(b0), "=r"(b1), "=r"(b2), "=r"(b3) : "r"(badr));
                asm volatile(
                    "mma.sync.aligned.m16n8k16.row.col.f32.f16.f16.f32 "
                    "{%0,%1,%2,%3},{%4,%5,%6,%7},{%8,%9},{%0,%1,%2,%3};"
                    : "+f"(acc[np * 2][0]), "+f"(acc[np * 2][1]),
                      "+f"(acc[np * 2][2]), "+f"(acc[np * 2][3])
                    : "r"(a0), "r"(a1), "r"(a2), "r"(a3), "r"(b0), "r"(b1));
                asm volatile(
                    "mma.sync.aligned.m16n8k16.row.col.f32.f16.f16.f32 "
                    "{%0,%1,%2,%3},{%4,%5,%6,%7},{%8,%9},{%0,%1,%2,%3};"
                    : "+f"(acc[np * 2 + 1][0]), "+f"(acc[np * 2 + 1][1]),
                      "+f"(acc[np * 2 + 1][2]), "+f"(acc[np * 2 + 1][3])
                    : "r"(a0), "r"(a1), "r"(a2), "r"(a3), "r"(b2), "r"(b3));
            }
        }
        __syncthreads();
    }
    int r0 = row0 + wr + gid;
    int r1 = r0 + 8;
    #pragma unroll
    for (int nt = 0; nt < 16; nt++) {
        int col = nt * 8 + tig * 2;
        if (r0 < n)
            *reinterpret_cast<__half2*>(Y + r0 * ND + col) =
                __floats2half2_rn(acc[nt][0], acc[nt][1]);
        if (r1 < n)
            *reinterpret_cast<__half2*>(Y + r1 * ND + col) =
                __floats2half2_rn(acc[nt][2], acc[nt][3]);
    }
}

// -------- CSR pull aggregation: warp/node, fp16 gather, fp32 accum ---------
// out = di * ( self*di + sum_j val_j * msg_j ) + bias,  val_j = ew*dinv[src]
// Always writes fp16 (interior layers feed the GEMM; final layer feeds pool,
// where fp16 quantization averages out over ~780 nodes/graph).
__global__ void __launch_bounds__(256) k_agg(const __half* __restrict__ XW,
                                             const float* __restrict__ bias,
                                             __half* __restrict__ OUT,
                                             int n, int relu) {
    int node = (blockIdx.x * blockDim.x + threadIdx.x) >> 5;
    int lane = threadIdx.x & 31;
    if (node >= n) return;

    const uint2* XWv = reinterpret_cast<const uint2*>(XW);

    float di = g_dinv[node];
    float4 a = h4_to_f4(XWv[node * 32 + lane]);
    float4 acc = make_float4(a.x * di, a.y * di, a.z * di, a.w * di);

    int e0 = g_rowptr[node], e1 = g_rowptr[node + 1];
    int e = e0;
    for (; e + 8 <= e1; e += 8) {
        uint2 cv[8]; uint2 u[8];
        #pragma unroll
        for (int j = 0; j < 8; j++) cv[j] = g_csr[e + j];
        #pragma unroll
        for (int j = 0; j < 8; j++) u[j] = XWv[cv[j].x * 32 + lane];
        #pragma unroll
        for (int j = 0; j < 8; j++) {
            float v = __uint_as_float(cv[j].y);
            float4 m = h4_to_f4(u[j]);
            acc.x = fmaf(v, m.x, acc.x); acc.y = fmaf(v, m.y, acc.y);
            acc.z = fmaf(v, m.z, acc.z); acc.w = fmaf(v, m.w, acc.w);
        }
    }
    if (e + 4 <= e1) {
        uint2 cv[4]; uint2 u[4];
        #pragma unroll
        for (int j = 0; j < 4; j++) cv[j] = g_csr[e + j];
        #pragma unroll
        for (int j = 0; j < 4; j++) u[j] = XWv[cv[j].x * 32 + lane];
        #pragma unroll
        for (int j = 0; j < 4; j++) {
            float v = __uint_as_float(cv[j].y);
            float4 m = h4_to_f4(u[j]);
            acc.x = fmaf(v, m.x, acc.x); acc.y = fmaf(v, m.y, acc.y);
            acc.z = fmaf(v, m.z, acc.z); acc.w = fmaf(v, m.w, acc.w);
        }
        e += 4;
    }
    for (; e < e1; e++) {
        uint2 cv = g_csr[e];
        float v = __uint_as_float(cv.y);
        float4 m = h4_to_f4(XWv[cv.x * 32 + lane]);
        acc.x = fmaf(v, m.x, acc.x); acc.y = fmaf(v, m.y, acc.y);
        acc.z = fmaf(v, m.z, acc.z); acc.w = fmaf(v, m.w, acc.w);
    }
    float4 b = reinterpret_cast<const float4*>(bias)[lane];
    acc.x = fmaf(acc.x, di, b.x); acc.y = fmaf(acc.y, di, b.y);
    acc.z = fmaf(acc.z, di, b.z); acc.w = fmaf(acc.w, di, b.w);
    if (relu) {
        acc.x = fmaxf(acc.x, 0.f); acc.y = fmaxf(acc.y, 0.f);
        acc.z = fmaxf(acc.z, 0.f); acc.w = fmaxf(acc.w, 0.f);
    }
    uint2 o;
    __half2 h0 = __floats2half2_rn(acc.x, acc.y);
    __half2 h1 = __floats2half2_rn(acc.z, acc.w);
    o.x = *reinterpret_cast<unsigned*>(&h0);
    o.y = *reinterpret_cast<unsigned*>(&h1);
    reinterpret_cast<uint2*>(OUT)[node * 32 + lane] = o;
}

// -------- global mean pool (fp16 input): 1024 thr/graph, fused bounds ------
__global__ void __launch_bounds__(1024) k_pool(const __half* __restrict__ h,
                                               const int* __restrict__ batch,
                                               int n, float4* __restrict__ out) {
    __shared__ float4 part[32][32];
    __shared__ int sse[2];
    int g = blockIdx.x;
    if (threadIdx.x < 2) {
        int target = g + threadIdx.x;
        int lo = 0, hi = n;
        while (lo < hi) {
            int mid = (lo + hi) >> 1;
            if (batch[mid] < target) lo = mid + 1; else hi = mid;
        }
        sse[threadIdx.x] = lo;
    }
    __syncthreads();
    int s = sse[0], e = sse[1];
    int rg = threadIdx.x >> 5;
    int ch = threadIdx.x & 31;
    const uint2* hv = reinterpret_cast<const uint2*>(h);
    float4 acc = make_float4(0.f, 0.f, 0.f, 0.f);
    for (int i = s + rg; i < e; i += 32) {
        float4 v = h4_to_f4(hv[i * 32 + ch]);
        acc.x += v.x; acc.y += v.y; acc.z += v.z; acc.w += v.w;
    }
    part[rg][ch] = acc;
    __syncthreads();
    #pragma unroll
    for (int off = 16; off > 0; off >>= 1) {
        if (rg < off) {
            float4 o = part[rg + off][ch];
            float4 m = part[rg][ch];
            m.x += o.x; m.y += o.y; m.z += o.z; m.w += o.w;
            part[rg][ch] = m;
        }
        __syncthreads();
    }
    if (rg == 0) {
        float inv = 1.0f / (float)((e - s) > 0 ? (e - s) : 1);
        float4 m = part[0][ch];
        m.x *= inv; m.y *= inv; m.z *= inv; m.w *= inv;
        out[g * 32 + ch] = m;
    }
}

extern "C" void kernel_launch(void* const* d_in, const int* in_sizes, int n_in,
                              void* d_out, int out_size) {
    const float* x     = (const float*)d_in[0];
    const int*   ei    = (const int*)d_in[1];
    const float* ew    = (const float*)d_in[2];
    const int*   batch = (const int*)d_in[3];
    const float* W0    = (const float*)d_in[4];
    const float* b0    = (const float*)d_in[5];
    const float* W1    = (const float*)d_in[6];
    const float* b1    = (const float*)d_in[7];
    const float* W2    = (const float*)d_in[8];
    const float* b2    = (const float*)d_in[9];

    int n = in_sizes[0] / ND;
    int E = in_sizes[1] / 2;
    int ngraphs = out_size / ND;
    const int* src = ei;
    const int* dst = ei + E;

    __half *bufH, *bufH2;
    cudaGetSymbolAddress((void**)&bufH,  g_bufH);
    cudaGetSymbolAddress((void**)&bufH2, g_bufH2);

    int eb  = (E + 255) / 256;
    int gb  = (n + 127) / 128;
    int ab  = (int)(((long long)n * 32 + 255) / 256);
    int sbk = (n + SCANB - 1) / SCANB;

    // Fork: layer-0 GEMM (depends only on x, W0) runs on a side stream,
    // overlapped with the CSR/normalization build on the main stream.
    cudaStream_t s1;
    cudaStreamCreate(&s1);
    cudaEvent_t eFork, eJoin;
    cudaEventCreateWithFlags(&eFork, cudaEventDisableTiming);
    cudaEventCreateWithFlags(&eJoin, cudaEventDisableTiming);

    cudaEventRecord(eFork, 0);
    cudaStreamWaitEvent(s1, eFork, 0);
    k_gemm<false><<<gb, 256, 0, s1>>>(x, W0, bufH, n);
    cudaEventRecord(eJoin, s1);

    // normalization + CSR build (g_deg/g_cnt zeroed by protocol)
    k_deg<<<eb, 256>>>(dst, ew, E);
    k_scanA<<<sbk, SCANB>>>(n);
    k_scanC<<<sbk, SCANB>>>(n);
    k_csr<<<eb, 256>>>(src, dst, ew, E);

    cudaStreamWaitEvent(0, eJoin, 0);   // join before layer-0 aggregation

    // layer 0 agg -> fp16 interior
    k_agg<<<ab, 256>>>(bufH, b0, bufH2, n, 1);
    // layer 1
    k_gemm<true><<<gb, 256>>>(bufH2, W1, bufH, n);
    k_agg<<<ab, 256>>>(bufH, b1, bufH2, n, 1);
    // layer 2 (final agg also fp16; pool averages out the quantization)
    k_gemm<true><<<gb, 256>>>(bufH2, W2, bufH, n);
    k_agg<<<ab, 256>>>(bufH, b2, bufH2, n, 0);

    // pooling (bounds fused, fp16 input)
    k_pool<<<ngraphs, 1024>>>(bufH2, batch, n, (float4*)d_out);

    cudaEventDestroy(eFork);
    cudaEventDestroy(eJoin);
    cudaStreamDestroy(s1);
}

// round 17
// speedup vs baseline: 1.6307x; 1.0559x over previous
#include <cuda_runtime.h>
#include <cuda_fp16.h>

#define ND        128
#define MAXN      50016
#define MAXE      1600000
#define SCANB     1024
#define MAXBLK    64

// -------- device scratch (no allocation allowed) --------
// Zero-restore protocol: g_pack and g_arrive are zero at module load;
// k_deg accumulates, k_scanA consumes AND re-zeroes g_pack; the last
// k_scanA block re-zeroes g_arrive. Every graph replay sees identical state.
__device__ unsigned long long g_pack[MAXN];   // {cnt:24, deg_fx24:40}
__device__ unsigned int g_arrive;
__device__ float g_dinv[MAXN];
__device__ int   g_row0[MAXN];          // block-local exclusive edge offset
__device__ int   g_cntS[MAXN];          // per-node edge count
__device__ int   g_bsum[MAXBLK];
__device__ int   g_boff[MAXBLK];        // cross-block exclusive offsets
__device__ int   g_rank[MAXE];          // per-edge rank within its dst segment
__device__ uint2 g_csr[MAXE];           // packed {src, val_bits}, val = ew*dinv[src]
__device__ __align__(256) __half g_bufH [50000 * ND];  // fp16: messages ping
__device__ __align__(256) __half g_bufH2[50000 * ND];  // fp16: messages pong

#define DEG_SCALE 16777216.0f           // 2^24
#define DEG_MASK  ((1ULL << 40) - 1ULL)

__device__ __forceinline__ unsigned saddr(const void* p) {
    return (unsigned)__cvta_generic_to_shared(p);
}

__device__ __forceinline__ float4 h4_to_f4(uint2 u) {
    __half2 a = *reinterpret_cast<__half2*>(&u.x);
    __half2 b = *reinterpret_cast<__half2*>(&u.y);
    float2 fa = __half22float2(a);
    float2 fb = __half22float2(b);
    return make_float4(fa.x, fa.y, fb.x, fb.y);
}

// -------- degree + count + rank in ONE packed 64-bit atomic per edge -------
__global__ void k_deg(const int* __restrict__ dst, const float* __restrict__ ew, int E) {
    int e = blockIdx.x * blockDim.x + threadIdx.x;
    if (e < E) {
        int d = dst[e];
        unsigned long long add =
            (1ULL << 40) | (unsigned long long)(long long)(ew[e] * DEG_SCALE);
        unsigned long long old = atomicAdd(&g_pack[d], add);
        g_rank[e] = (int)(old >> 40);   // previous count = CSR slot rank
    }
}

// -------- scanA: dinv + block-local exclusive scan + last-block boff scan --
__global__ void k_scanA(int n) {
    __shared__ int warp_sums[32];
    __shared__ int s_carry;
    __shared__ unsigned s_rank;
    int tid = threadIdx.x;
    int lane = tid & 31, wid = tid >> 5;
    int i = blockIdx.x * SCANB + tid;
    int x = 0;
    if (i < n) {
        unsigned long long p = g_pack[i];
        g_pack[i] = 0ULL;                       // restore protocol invariant
        x = (int)(p >> 40);
        float d = (float)(p & DEG_MASK) * (1.0f / DEG_SCALE) + 1.0f; // + self-loop
        g_dinv[i] = rsqrtf(d);
        g_cntS[i] = x;
    }
    int inc = x;
    #pragma unroll
    for (int o = 1; o < 32; o <<= 1) {
        int y = __shfl_up_sync(0xFFFFFFFFu, inc, o);
        if (lane >= o) inc += y;
    }
    if (lane == 31) warp_sums[wid] = inc;
    __syncthreads();
    if (wid == 0) {
        int w = warp_sums[lane];
        #pragma unroll
        for (int o = 1; o < 32; o <<= 1) {
            int y = __shfl_up_sync(0xFFFFFFFFu, w, o);
            if (lane >= o) w += y;
        }
        warp_sums[lane] = w;
    }
    __syncthreads();
    int incl = inc + (wid > 0 ? warp_sums[wid - 1] : 0);
    if (i < n) g_row0[i] = incl - x;            // block-local EXCLUSIVE
    if (tid == SCANB - 1) g_bsum[blockIdx.x] = incl;
    // ---- last-arriving block computes the <=49-entry block-offset scan ----
    __syncthreads();
    if (tid == 0) {
        __threadfence();                        // publish g_bsum/g_row0/g_dinv
        s_rank = atomicAdd(&g_arrive, 1u);
    }
    __syncthreads();
    if (s_rank == gridDim.x - 1) {              // uniform: whole block enters
        __threadfence();                        // see all other blocks' g_bsum
        int nblk = gridDim.x;
        int v = 0, sx = 0;
        if (tid < 64) {
            v = (tid < nblk) ? g_bsum[tid] : 0;
            sx = v;
            #pragma unroll
            for (int o = 1; o < 32; o <<= 1) {
                int y = __shfl_up_sync(0xFFFFFFFFu, sx, o);
                if ((tid & 31) >= o) sx += y;
            }
            if (tid == 31) s_carry = sx;        // inclusive sum of first warp
        }
        __syncthreads();
        if (tid < 64) {
            if (tid >= 32) sx += s_carry;
            if (tid < nblk) g_boff[tid] = sx - v;   // exclusive
        }
        if (tid == 0) atomicExch(&g_arrive, 0u);    // restore invariant
    }
}

// -------- scatter edges into CSR (by dst): NO atomics, packed 8B store -----
__global__ void k_csr(const int* __restrict__ src, const int* __restrict__ dst,
                      const float* __restrict__ ew, int E) {
    int e = blockIdx.x * blockDim.x + threadIdx.x;
    if (e < E) {
        int s = src[e], d = dst[e];
        int p = g_row0[d] + g_boff[d >> 10] + g_rank[e];
        uint2 u;
        u.x = (unsigned)s;
        float v = g_dinv[s] * ew[e];
        u.y = __float_as_uint(v);
        g_csr[p] = u;
    }
}

// -------- fp16 tensor-core GEMM via ldmatrix + mma.m16n8k16 --------
template<bool HALF_IN>
__global__ void __launch_bounds__(256) k_gemm(const void* __restrict__ Xv,
                                              const float* __restrict__ W,
                                              __half* __restrict__ Y, int n) {
    __shared__ __align__(16) __half Xs[128][72];    // pitch 144B
    __shared__ __align__(16) __half Ws[64][136];    // pitch 272B
    const int tid  = threadIdx.x;
    const int warp = tid >> 5, lane = tid & 31;
    const int gid  = lane >> 2, tig = lane & 3;
    const int row0 = blockIdx.x * 128;
    const int wr   = warp * 16;

    float acc[16][4];
    #pragma unroll
    for (int t = 0; t < 16; t++)
        #pragma unroll
        for (int j = 0; j < 4; j++) acc[t][j] = 0.0f;

    for (int kc = 0; kc < ND; kc += 64) {
        #pragma unroll
        for (int i = 0; i < 8; i++) {
            int idx = tid + i * 256;
            int k   = idx >> 5;
            int c4  = (idx & 31) * 4;
            float4 v = *reinterpret_cast<const float4*>(W + (kc + k) * ND + c4);
            *reinterpret_cast<__half2*>(&Ws[k][c4])     = __floats2half2_rn(v.x, v.y);
            *reinterpret_cast<__half2*>(&Ws[k][c4 + 2]) = __floats2half2_rn(v.z, v.w);
        }
        if (HALF_IN) {
            const __half* X = (const __half*)Xv;
            #pragma unroll
            for (int i = 0; i < 4; i++) {
                int idx = tid + i * 256;
                int m   = idx >> 3;
                int j8  = (idx & 7) * 8;
                uint4 v = make_uint4(0, 0, 0, 0);
                if (row0 + m < n)
                    v = *reinterpret_cast<const uint4*>(X + (row0 + m) * ND + kc + j8);
                *reinterpret_cast<uint4*>(&Xs[m][j8]) = v;
            }
        } else {
            const float* X = (const float*)Xv;
            #pragma unroll
            for (int i = 0; i < 8; i++) {
                int idx = tid + i * 256;
                int m   = idx >> 4;
                int j4  = (idx & 15) * 4;
                float4 v = make_float4(0.f, 0.f, 0.f, 0.f);
                if (row0 + m < n)
                    v = *reinterpret_cast<const float4*>(X + (row0 + m) * ND + kc + j4);
                *reinterpret_cast<__half2*>(&Xs[m][j4])     = __floats2half2_rn(v.x, v.y);
                *reinterpret_cast<__half2*>(&Xs[m][j4 + 2]) = __floats2half2_rn(v.z, v.w);
            }
        }
        __syncthreads();
        #pragma unroll
        for (int ks = 0; ks < 4; ks++) {
            int k0 = ks * 16;
            unsigned a0, a1, a2, a3;
            unsigned aadr = saddr(&Xs[wr + (lane & 15)][k0 + (lane >> 4) * 8]);
            asm volatile("ldmatrix.sync.aligned.m8n8.x4.shared.b16 {%0,%1,%2,%3}, [%4];"
                         : "=r"(a0), "=r"(a1), "=r"(a2), "=r"(a3) : "r"(aadr));
            #pragma unroll
            for (int np = 0; np < 8; np++) {
                unsigned b0, b1, b2, b3;
                unsigned badr = saddr(&Ws[k0 + (lane & 15)][np * 16 + (lane >> 4) * 8]);
                asm volatile("ldmatrix.sync.aligned.m8n8.x4.trans.shared.b16 {%0,%1,%2,%3}, [%4];"
                             : "=r"(b0), "=r"(b1), "=r"(b2), "=r"(b3) : "r"(badr));
                asm volatile(
                    "mma.sync.aligned.m16n8k16.row.col.f32.f16.f16.f32 "
                    "{%0,%1,%2,%3},{%4,%5,%6,%7},{%8,%9},{%0,%1,%2,%3};"
                    : "+f"(acc[np * 2][0]), "+f"(acc[np * 2][1]),
                      "+f"(acc[np * 2][2]), "+f"(acc[np * 2][3])
                    : "r"(a0), "r"(a1), "r"(a2), "r"(a3), "r"(b0), "r"(b1));
                asm volatile(
                    "mma.sync.aligned.m16n8k16.row.col.f32.f16.f16.f32 "
                    "{%0,%1,%2,%3},{%4,%5,%6,%7},{%8,%9},{%0,%1,%2,%3};"
                    : "+f"(acc[np * 2 + 1][0]), "+f"(acc[np * 2 + 1][1]),
                      "+f"(acc[np * 2 + 1][2]), "+f"(acc[np * 2 + 1][3])
                    : "r"(a0), "r"(a1), "r"(a2), "r"(a3), "r"(b2), "r"(b3));
            }
        }
        __syncthreads();
    }
    int r0 = row0 + wr + gid;
    int r1 = r0 + 8;
    #pragma unroll
    for (int nt = 0; nt < 16; nt++) {
        int col = nt * 8 + tig * 2;
        if (r0 < n)
            *reinterpret_cast<__half2*>(Y + r0 * ND + col) =
                __floats2half2_rn(acc[nt][0], acc[nt][1]);
        if (r1 < n)
            *reinterpret_cast<__half2*>(Y + r1 * ND + col) =
                __floats2half2_rn(acc[nt][2], acc[nt][3]);
    }
}

// -------- CSR pull aggregation: warp/node, fp16 gather, fp32 accum ---------
// out = di * ( self*di + sum_j val_j * msg_j ) + bias,  val_j = ew*dinv[src]
__global__ void __launch_bounds__(256) k_agg(const __half* __restrict__ XW,
                                             const float* __restrict__ bias,
                                             __half* __restrict__ OUT,
                                             int n, int relu) {
    int node = (blockIdx.x * blockDim.x + threadIdx.x) >> 5;
    int lane = threadIdx.x & 31;
    if (node >= n) return;

    const uint2* XWv = reinterpret_cast<const uint2*>(XW);

    float di = g_dinv[node];
    float4 a = h4_to_f4(XWv[node * 32 + lane]);
    float4 acc = make_float4(a.x * di, a.y * di, a.z * di, a.w * di);

    int e0 = g_row0[node] + g_boff[node >> 10];
    int e1 = e0 + g_cntS[node];
    int e = e0;
    for (; e + 8 <= e1; e += 8) {
        uint2 cv[8]; uint2 u[8];
        #pragma unroll
        for (int j = 0; j < 8; j++) cv[j] = g_csr[e + j];
        #pragma unroll
        for (int j = 0; j < 8; j++) u[j] = XWv[cv[j].x * 32 + lane];
        #pragma unroll
        for (int j = 0; j < 8; j++) {
            float v = __uint_as_float(cv[j].y);
            float4 m = h4_to_f4(u[j]);
            acc.x = fmaf(v, m.x, acc.x); acc.y = fmaf(v, m.y, acc.y);
            acc.z = fmaf(v, m.z, acc.z); acc.w = fmaf(v, m.w, acc.w);
        }
    }
    if (e + 4 <= e1) {
        uint2 cv[4]; uint2 u[4];
        #pragma unroll
        for (int j = 0; j < 4; j++) cv[j] = g_csr[e + j];
        #pragma unroll
        for (int j = 0; j < 4; j++) u[j] = XWv[cv[j].x * 32 + lane];
        #pragma unroll
        for (int j = 0; j < 4; j++) {
            float v = __uint_as_float(cv[j].y);
            float4 m = h4_to_f4(u[j]);
            acc.x = fmaf(v, m.x, acc.x); acc.y = fmaf(v, m.y, acc.y);
            acc.z = fmaf(v, m.z, acc.z); acc.w = fmaf(v, m.w, acc.w);
        }
        e += 4;
    }
    for (; e < e1; e++) {
        uint2 cv = g_csr[e];
        float v = __uint_as_float(cv.y);
        float4 m = h4_to_f4(XWv[cv.x * 32 + lane]);
        acc.x = fmaf(v, m.x, acc.x); acc.y = fmaf(v, m.y, acc.y);
        acc.z = fmaf(v, m.z, acc.z); acc.w = fmaf(v, m.w, acc.w);
    }
    float4 b = reinterpret_cast<const float4*>(bias)[lane];
    acc.x = fmaf(acc.x, di, b.x); acc.y = fmaf(acc.y, di, b.y);
    acc.z = fmaf(acc.z, di, b.z); acc.w = fmaf(acc.w, di, b.w);
    if (relu) {
        acc.x = fmaxf(acc.x, 0.f); acc.y = fmaxf(acc.y, 0.f);
        acc.z = fmaxf(acc.z, 0.f); acc.w = fmaxf(acc.w, 0.f);
    }
    uint2 o;
    __half2 h0 = __floats2half2_rn(acc.x, acc.y);
    __half2 h1 = __floats2half2_rn(acc.z, acc.w);
    o.x = *reinterpret_cast<unsigned*>(&h0);
    o.y = *reinterpret_cast<unsigned*>(&h1);
    reinterpret_cast<uint2*>(OUT)[node * 32 + lane] = o;
}

// -------- global mean pool (fp16 input): 1024 thr/graph, fused bounds ------
__global__ void __launch_bounds__(1024) k_pool(const __half* __restrict__ h,
                                               const int* __restrict__ batch,
                                               int n, float4* __restrict__ out) {
    __shared__ float4 part[32][32];
    __shared__ int sse[2];
    int g = blockIdx.x;
    if (threadIdx.x < 2) {
        int target = g + threadIdx.x;
        int lo = 0, hi = n;
        while (lo < hi) {
            int mid = (lo + hi) >> 1;
            if (batch[mid] < target) lo = mid + 1; else hi = mid;
        }
        sse[threadIdx.x] = lo;
    }
    __syncthreads();
    int s = sse[0], e = sse[1];
    int rg = threadIdx.x >> 5;
    int ch = threadIdx.x & 31;
    const uint2* hv = reinterpret_cast<const uint2*>(h);
    float4 acc = make_float4(0.f, 0.f, 0.f, 0.f);
    for (int i = s + rg; i < e; i += 32) {
        float4 v = h4_to_f4(hv[i * 32 + ch]);
        acc.x += v.x; acc.y += v.y; acc.z += v.z; acc.w += v.w;
    }
    part[rg][ch] = acc;
    __syncthreads();
    #pragma unroll
    for (int off = 16; off > 0; off >>= 1) {
        if (rg < off) {
            float4 o = part[rg + off][ch];
            float4 m = part[rg][ch];
            m.x += o.x; m.y += o.y; m.z += o.z; m.w += o.w;
            part[rg][ch] = m;
        }
        __syncthreads();
    }
    if (rg == 0) {
        float inv = 1.0f / (float)((e - s) > 0 ? (e - s) : 1);
        float4 m = part[0][ch];
        m.x *= inv; m.y *= inv; m.z *= inv; m.w *= inv;
        out[g * 32 + ch] = m;
    }
}

extern "C" void kernel_launch(void* const* d_in, const int* in_sizes, int n_in,
                              void* d_out, int out_size) {
    const float* x     = (const float*)d_in[0];
    const int*   ei    = (const int*)d_in[1];
    const float* ew    = (const float*)d_in[2];
    const int*   batch = (const int*)d_in[3];
    const float* W0    = (const float*)d_in[4];
    const float* b0    = (const float*)d_in[5];
    const float* W1    = (const float*)d_in[6];
    const float* b1    = (const float*)d_in[7];
    const float* W2    = (const float*)d_in[8];
    const float* b2    = (const float*)d_in[9];

    int n = in_sizes[0] / ND;
    int E = in_sizes[1] / 2;
    int ngraphs = out_size / ND;
    const int* src = ei;
    const int* dst = ei + E;

    __half *bufH, *bufH2;
    cudaGetSymbolAddress((void**)&bufH,  g_bufH);
    cudaGetSymbolAddress((void**)&bufH2, g_bufH2);

    int eb  = (E + 255) / 256;
    int gb  = (n + 127) / 128;
    int ab  = (int)(((long long)n * 32 + 255) / 256);
    int sbk = (n + SCANB - 1) / SCANB;

    // Fork: layer-0 GEMM (depends only on x, W0) overlaps the CSR build.
    cudaStream_t s1;
    cudaStreamCreate(&s1);
    cudaEvent_t eFork, eJoin;
    cudaEventCreateWithFlags(&eFork, cudaEventDisableTiming);
    cudaEventCreateWithFlags(&eJoin, cudaEventDisableTiming);

    cudaEventRecord(eFork, 0);
    cudaStreamWaitEvent(s1, eFork, 0);
    k_gemm<false><<<gb, 256, 0, s1>>>(x, W0, bufH, n);
    cudaEventRecord(eJoin, s1);

    // normalization + CSR build (packed atomics; scanC folded into scanA)
    k_deg<<<eb, 256>>>(dst, ew, E);
    k_scanA<<<sbk, SCANB>>>(n);
    k_csr<<<eb, 256>>>(src, dst, ew, E);

    cudaStreamWaitEvent(0, eJoin, 0);   // join before layer-0 aggregation

    // layer 0 agg -> fp16 interior
    k_agg<<<ab, 256>>>(bufH, b0, bufH2, n, 1);
    // layer 1
    k_gemm<true><<<gb, 256>>>(bufH2, W1, bufH, n);
    k_agg<<<ab, 256>>>(bufH, b1, bufH2, n, 1);
    // layer 2 (final agg also fp16; pool averages out the quantization)
    k_gemm<true><<<gb, 256>>>(bufH2, W2, bufH, n);
    k_agg<<<ab, 256>>>(bufH, b2, bufH2, n, 0);

    // pooling (bounds fused, fp16 input)
    k_pool<<<ngraphs, 1024>>>(bufH2, batch, n, (float4*)d_out);

    cudaEventDestroy(eFork);
    cudaEventDestroy(eJoin);
    cudaStreamDestroy(s1);
}